// round 13
// baseline (speedup 1.0000x reference)
#include <cuda_runtime.h>
#include <cuda_fp16.h>
#include <cstdint>

#define SEQ   256
#define BATCH 8192

// pack two f32 -> f16x2 (lo = first arg)
__device__ __forceinline__ uint32_t pkh(float lo, float hi) {
    uint32_t u; asm("cvt.rn.f16x2.f32 %0, %2, %1;" : "=r"(u) : "f"(lo), "f"(hi)); return u;
}
// 8x8 f16 in-warp transpose
__device__ __forceinline__ uint32_t movm(uint32_t s) {
    uint32_t d;
    asm("movmatrix.sync.aligned.m8n8.trans.b16 %0, %1;" : "=r"(d) : "r"(s));
    return d;
}
// D += A*B
__device__ __forceinline__ void mma16(float d[4], const uint32_t a[4],
                                      uint32_t b0, uint32_t b1) {
    asm("mma.sync.aligned.m16n8k16.row.col.f32.f16.f16.f32 "
        "{%0,%1,%2,%3},{%4,%5,%6,%7},{%8,%9},{%0,%1,%2,%3};"
        : "+f"(d[0]), "+f"(d[1]), "+f"(d[2]), "+f"(d[3])
        : "r"(a[0]), "r"(a[1]), "r"(a[2]), "r"(a[3]), "r"(b0), "r"(b1));
}
// D = A*B (fresh accumulator)
__device__ __forceinline__ void mma16o(float d[4], const uint32_t a[4],
                                       uint32_t b0, uint32_t b1) {
    asm("mma.sync.aligned.m16n8k16.row.col.f32.f16.f16.f32 "
        "{%0,%1,%2,%3},{%4,%5,%6,%7},{%8,%9},{%10,%10,%10,%10};"
        : "=f"(d[0]), "=f"(d[1]), "=f"(d[2]), "=f"(d[3])
        : "r"(a[0]), "r"(a[1]), "r"(a[2]), "r"(a[3]), "r"(b0), "r"(b1),
          "f"(0.0f));
}
// f32 gates: sigmoid(x) = 0.5*tanh(0.5x)+0.5
__device__ __forceinline__ float sig_t(float x) {
    float t; asm("tanh.approx.f32 %0, %1;" : "=f"(t) : "f"(0.5f * x));
    return fmaf(t, 0.5f, 0.5f);
}
__device__ __forceinline__ float tanh_ap(float x) {
    float t; asm("tanh.approx.f32 %0, %1;" : "=f"(t) : "f"(x)); return t;
}

// Grid: 148 blocks x 224 threads (7 warps). Warp-unit W = wid*148 + bid,
// active iff W < 1024; warp privately owns 8 batch columns [8W, 8W+8).
// D[hidden(m), batch(n)] = W[hidden,k] @ h[k,batch]; movmatrix recurrence,
// no smem exchange, no barriers in the loop.
// Pipeline rotation: Wh x hB1 MMAs for step t+1 issue at the BOTTOM of step t,
// before the y shuffle-reduce/store, so the shuffle tail hides under tensor work.
__global__ void __launch_bounds__(224, 1) gru2_wp4_kernel(
    const float* __restrict__ x,
    const float* __restrict__ h_in,
    const float* __restrict__ Wih0,
    const float* __restrict__ Whh0,
    const float* __restrict__ bih0,
    const float* __restrict__ bhh0,
    const float* __restrict__ Wih1,
    const float* __restrict__ Whh1,
    const float* __restrict__ bih1,
    const float* __restrict__ bhh1,
    const float* __restrict__ Wout,
    const float* __restrict__ bout,
    float* __restrict__ out)
{
    __shared__ float4 KA[32];   // (Wih0_r, Wih0_z, Wih0_n, bih0_n)
    __shared__ float4 KB[32];   // (br0c, bz0c, bhn0, Wout)
    __shared__ float4 KC[32];   // (br1c, bz1c, bin1, bhn1)
    __shared__ float  boS;

    const int tid = threadIdx.x;
    if (tid < 32) {
        int u = tid;
        KA[u] = make_float4(Wih0[u], Wih0[32 + u], Wih0[64 + u], bih0[64 + u]);
        KB[u] = make_float4(bih0[u] + bhh0[u], bih0[32 + u] + bhh0[32 + u],
                            bhh0[64 + u], Wout[u]);
        KC[u] = make_float4(bih1[u] + bhh1[u], bih1[32 + u] + bhh1[32 + u],
                            bih1[64 + u], bhh1[64 + u]);
    }
    if (tid == 0) boS = bout[0];
    __syncthreads();

    const int wid  = tid >> 5;
    const int lane = tid & 31;
    const int W = wid * 148 + blockIdx.x;
    if (W >= 1024) return;

    const int g  = lane >> 2;
    const int tg = lane & 3;
    const int base = W * 8;
    const float bo = boS;

    // ---- weight A-fragments, register-resident (36 tiles x 4 regs) ----
    uint32_t W0[3][2][2][4], Wi[3][2][2][4], Wh[3][2][2][4];
#pragma unroll
    for (int gate = 0; gate < 3; gate++)
#pragma unroll
        for (int mt = 0; mt < 2; mt++)
#pragma unroll
            for (int kt = 0; kt < 2; kt++)
#pragma unroll
                for (int aa = 0; aa < 4; aa++) {
                    int row = gate * 32 + mt * 16 + g + (aa & 1) * 8;
                    int col = kt * 16 + 2 * tg + (aa >> 1) * 8;
                    float2 v0 = *(const float2*)&Whh0[row * 32 + col];
                    float2 vi = *(const float2*)&Wih1[row * 32 + col];
                    float2 vh = *(const float2*)&Whh1[row * 32 + col];
                    W0[gate][mt][kt][aa] = pkh(v0.x, v0.y);
                    Wi[gate][mt][kt][aa] = pkh(vi.x, vi.y);
                    Wh[gate][mt][kt][aa] = pkh(vh.x, vh.y);
                }

    // ---- h masters (f32, D-layout) ----
    float h0D[2][4], h1D[2][4];
#pragma unroll
    for (int mt = 0; mt < 2; mt++)
#pragma unroll
        for (int rr = 0; rr < 2; rr++)
#pragma unroll
            for (int c = 0; c < 2; c++) {
                int u = 16 * mt + 8 * rr + g;
                int b = base + 2 * tg + c;
                h0D[mt][rr * 2 + c] = h_in[(size_t)b * 32 + u];
                h1D[mt][rr * 2 + c] = h_in[(size_t)(BATCH + b) * 32 + u];
            }

    // ---- B-fragments via transpose ----
    uint32_t hB0[4], hB1[4];
#pragma unroll
    for (int mt = 0; mt < 2; mt++) {
        hB0[mt * 2]     = movm(pkh(h0D[mt][0], h0D[mt][1]));
        hB0[mt * 2 + 1] = movm(pkh(h0D[mt][2], h0D[mt][3]));
        hB1[mt * 2]     = movm(pkh(h1D[mt][0], h1D[mt][1]));
        hB1[mt * 2 + 1] = movm(pkh(h1D[mt][2], h1D[mt][3]));
    }

    float2 xv = *(const float2*)&x[base + 2 * tg];

    // ---- preamble: first Wh x h1 contributions ----
    float Er[2][4], Ez[2][4], Eh[2][4];
#pragma unroll
    for (int mt = 0; mt < 2; mt++) {
        mma16o(Er[mt], Wh[0][mt][0], hB1[0], hB1[1]);
        mma16 (Er[mt], Wh[0][mt][1], hB1[2], hB1[3]);
        mma16o(Ez[mt], Wh[1][mt][0], hB1[0], hB1[1]);
        mma16 (Ez[mt], Wh[1][mt][1], hB1[2], hB1[3]);
        mma16o(Eh[mt], Wh[2][mt][0], hB1[0], hB1[1]);
        mma16 (Eh[mt], Wh[2][mt][1], hB1[2], hB1[3]);
    }

    for (int st = 0; st < SEQ; st++) {
        float2 xn = *(const float2*)&x[(size_t)min(st + 1, SEQ - 1) * BATCH + base + 2 * tg];

        // ---------- layer 0: per-mt MMA + epilogue ----------
#pragma unroll
        for (int mt = 0; mt < 2; mt++) {
            float Dr[4], Dz[4], Dn[4];
            mma16o(Dr, W0[0][mt][0], hB0[0], hB0[1]);
            mma16 (Dr, W0[0][mt][1], hB0[2], hB0[3]);
            mma16o(Dz, W0[1][mt][0], hB0[0], hB0[1]);
            mma16 (Dz, W0[1][mt][1], hB0[2], hB0[3]);
            mma16o(Dn, W0[2][mt][0], hB0[0], hB0[1]);
            mma16 (Dn, W0[2][mt][1], hB0[2], hB0[3]);
#pragma unroll
            for (int rr = 0; rr < 2; rr++) {
                const int u = 16 * mt + 8 * rr + g;
                const float4 A  = KA[u];
                const float4 Bc = KB[u];
#pragma unroll
                for (int c = 0; c < 2; c++) {
                    const int di = rr * 2 + c;
                    const float xvc = c ? xv.y : xv.x;
                    float r = sig_t(fmaf(xvc, A.x, Dr[di] + Bc.x));
                    float z = sig_t(fmaf(xvc, A.y, Dz[di] + Bc.y));
                    float n = tanh_ap(fmaf(xvc, A.z, A.w) + r * (Dn[di] + Bc.z));
                    float hold = h0D[mt][di];
                    h0D[mt][di] = n + z * (hold - n);
                }
            }
        }
        // h0' -> B-frags (in-warp transpose)
#pragma unroll
        for (int mt = 0; mt < 2; mt++) {
            hB0[mt * 2]     = movm(pkh(h0D[mt][0], h0D[mt][1]));
            hB0[mt * 2 + 1] = movm(pkh(h0D[mt][2], h0D[mt][3]));
        }

        // ---------- layer 1: Wi x h0' appended, then epilogue ----------
        float y0 = 0.0f, y1 = 0.0f;
#pragma unroll
        for (int mt = 0; mt < 2; mt++) {
            float Ei[4];
            mma16 (Er[mt], Wi[0][mt][0], hB0[0], hB0[1]);
            mma16 (Er[mt], Wi[0][mt][1], hB0[2], hB0[3]);
            mma16 (Ez[mt], Wi[1][mt][0], hB0[0], hB0[1]);
            mma16 (Ez[mt], Wi[1][mt][1], hB0[2], hB0[3]);
            mma16o(Ei,     Wi[2][mt][0], hB0[0], hB0[1]);
            mma16 (Ei,     Wi[2][mt][1], hB0[2], hB0[3]);
#pragma unroll
            for (int rr = 0; rr < 2; rr++) {
                const int u = 16 * mt + 8 * rr + g;
                const float4 C = KC[u];
                const float wou = KB[u].w;
#pragma unroll
                for (int c = 0; c < 2; c++) {
                    const int di = rr * 2 + c;
                    float r = sig_t(Er[mt][di] + C.x);
                    float z = sig_t(Ez[mt][di] + C.y);
                    float n = tanh_ap(Ei[di] + C.z + r * (Eh[mt][di] + C.w));
                    float hold = h1D[mt][di];
                    float hn = n + z * (hold - n);
                    h1D[mt][di] = hn;
                    if (c) y1 = fmaf(hn, wou, y1); else y0 = fmaf(hn, wou, y0);
                }
            }
        }
        // h1' -> B-frags
#pragma unroll
        for (int mt = 0; mt < 2; mt++) {
            hB1[mt * 2]     = movm(pkh(h1D[mt][0], h1D[mt][1]));
            hB1[mt * 2 + 1] = movm(pkh(h1D[mt][2], h1D[mt][3]));
        }

        // ===== ROTATED HOIST: next step's Wh x h1' MMAs issue BEFORE the =====
        // ===== y shuffle-reduce, covering its 26-cyc-per-hop latency.     =====
#pragma unroll
        for (int mt = 0; mt < 2; mt++) {
            mma16o(Er[mt], Wh[0][mt][0], hB1[0], hB1[1]);
            mma16 (Er[mt], Wh[0][mt][1], hB1[2], hB1[3]);
            mma16o(Ez[mt], Wh[1][mt][0], hB1[0], hB1[1]);
            mma16 (Ez[mt], Wh[1][mt][1], hB1[2], hB1[3]);
            mma16o(Eh[mt], Wh[2][mt][0], hB1[0], hB1[1]);
            mma16 (Eh[mt], Wh[2][mt][1], hB1[2], hB1[3]);
        }

        // y reduce over g (lane bits 2,3,4) and store
        y0 += __shfl_xor_sync(0xffffffffu, y0, 4);
        y0 += __shfl_xor_sync(0xffffffffu, y0, 8);
        y0 += __shfl_xor_sync(0xffffffffu, y0, 16);
        y1 += __shfl_xor_sync(0xffffffffu, y1, 4);
        y1 += __shfl_xor_sync(0xffffffffu, y1, 8);
        y1 += __shfl_xor_sync(0xffffffffu, y1, 16);
        if (lane < 4) {
            float2 yo = make_float2(y0 + bo, y1 + bo);
            *(float2*)&out[(size_t)st * BATCH + base + 2 * tg] = yo;
        }
        xv = xn;
    }

    // final h_state (2, B, 32)
    float* hout = out + (size_t)SEQ * BATCH;
#pragma unroll
    for (int mt = 0; mt < 2; mt++)
#pragma unroll
        for (int rr = 0; rr < 2; rr++)
#pragma unroll
            for (int c = 0; c < 2; c++) {
                int u = 16 * mt + 8 * rr + g;
                int b = base + 2 * tg + c;
                hout[(size_t)b * 32 + u] = h0D[mt][rr * 2 + c];
                hout[(size_t)(BATCH + b) * 32 + u] = h1D[mt][rr * 2 + c];
            }
}

extern "C" void kernel_launch(void* const* d_in, const int* in_sizes, int n_in,
                              void* d_out, int out_size) {
    (void)in_sizes; (void)n_in; (void)out_size;
    const float* x    = (const float*)d_in[0];
    const float* h    = (const float*)d_in[1];
    const float* Wih0 = (const float*)d_in[2];
    const float* Whh0 = (const float*)d_in[3];
    const float* bih0 = (const float*)d_in[4];
    const float* bhh0 = (const float*)d_in[5];
    const float* Wih1 = (const float*)d_in[6];
    const float* Whh1 = (const float*)d_in[7];
    const float* bih1 = (const float*)d_in[8];
    const float* bhh1 = (const float*)d_in[9];
    const float* Wout = (const float*)d_in[10];
    const float* bout = (const float*)d_in[11];

    // 148 blocks x 7 warps: 1024 warp-units x 8 batch = 8192; barrier-free loop
    gru2_wp4_kernel<<<148, 224>>>(x, h, Wih0, Whh0, bih0, bhh0,
                                  Wih1, Whh1, bih1, bhh1, Wout, bout,
                                  (float*)d_out);
}

// round 14
// speedup vs baseline: 1.0924x; 1.0924x over previous
#include <cuda_runtime.h>
#include <cuda_fp16.h>
#include <cstdint>

#define SEQ   256
#define BATCH 8192

// pack two f32 -> f16x2 (lo = first arg)
__device__ __forceinline__ uint32_t pkh(float lo, float hi) {
    uint32_t u; asm("cvt.rn.f16x2.f32 %0, %2, %1;" : "=r"(u) : "f"(lo), "f"(hi)); return u;
}
// 8x8 f16 in-warp transpose
__device__ __forceinline__ uint32_t movm(uint32_t s) {
    uint32_t d;
    asm("movmatrix.sync.aligned.m8n8.trans.b16 %0, %1;" : "=r"(d) : "r"(s));
    return d;
}
// D += A*B
__device__ __forceinline__ void mma16(float d[4], const uint32_t a[4],
                                      uint32_t b0, uint32_t b1) {
    asm("mma.sync.aligned.m16n8k16.row.col.f32.f16.f16.f32 "
        "{%0,%1,%2,%3},{%4,%5,%6,%7},{%8,%9},{%0,%1,%2,%3};"
        : "+f"(d[0]), "+f"(d[1]), "+f"(d[2]), "+f"(d[3])
        : "r"(a[0]), "r"(a[1]), "r"(a[2]), "r"(a[3]), "r"(b0), "r"(b1));
}
// D = A*B (fresh accumulator)
__device__ __forceinline__ void mma16o(float d[4], const uint32_t a[4],
                                       uint32_t b0, uint32_t b1) {
    asm("mma.sync.aligned.m16n8k16.row.col.f32.f16.f16.f32 "
        "{%0,%1,%2,%3},{%4,%5,%6,%7},{%8,%9},{%10,%10,%10,%10};"
        : "=f"(d[0]), "=f"(d[1]), "=f"(d[2]), "=f"(d[3])
        : "r"(a[0]), "r"(a[1]), "r"(a[2]), "r"(a[3]), "r"(b0), "r"(b1),
          "f"(0.0f));
}
// f32 gates: sigmoid(x) = 0.5*tanh(0.5x)+0.5
__device__ __forceinline__ float sig_t(float x) {
    float t; asm("tanh.approx.f32 %0, %1;" : "=f"(t) : "f"(0.5f * x));
    return fmaf(t, 0.5f, 0.5f);
}
__device__ __forceinline__ float tanh_ap(float x) {
    float t; asm("tanh.approx.f32 %0, %1;" : "=f"(t) : "f"(x)); return t;
}

// Grid: 128 blocks x 256 threads (8 warps) -> 1024 warp-units, UNIFORM
// (exactly 2 warps per SMSP on 128 SMs). Warp-unit G = blockIdx.x*8 + wid
// privately owns 8 batch columns [8G, 8G+8).
// D[hidden(m), batch(n)] = W[hidden,k] @ h[k,batch]; movmatrix recurrence,
// no smem exchange, no barriers in the loop. R12 body (hoist at step top).
__global__ void __launch_bounds__(256, 1) gru2_wp5_kernel(
    const float* __restrict__ x,
    const float* __restrict__ h_in,
    const float* __restrict__ Wih0,
    const float* __restrict__ Whh0,
    const float* __restrict__ bih0,
    const float* __restrict__ bhh0,
    const float* __restrict__ Wih1,
    const float* __restrict__ Whh1,
    const float* __restrict__ bih1,
    const float* __restrict__ bhh1,
    const float* __restrict__ Wout,
    const float* __restrict__ bout,
    float* __restrict__ out)
{
    __shared__ float4 KA[32];   // (Wih0_r, Wih0_z, Wih0_n, bih0_n)
    __shared__ float4 KB[32];   // (br0c, bz0c, bhn0, Wout)
    __shared__ float4 KC[32];   // (br1c, bz1c, bin1, bhn1)
    __shared__ float  boS;

    const int tid = threadIdx.x;
    if (tid < 32) {
        int u = tid;
        KA[u] = make_float4(Wih0[u], Wih0[32 + u], Wih0[64 + u], bih0[64 + u]);
        KB[u] = make_float4(bih0[u] + bhh0[u], bih0[32 + u] + bhh0[32 + u],
                            bhh0[64 + u], Wout[u]);
        KC[u] = make_float4(bih1[u] + bhh1[u], bih1[32 + u] + bhh1[32 + u],
                            bih1[64 + u], bhh1[64 + u]);
    }
    if (tid == 0) boS = bout[0];
    __syncthreads();

    const int wid  = tid >> 5;
    const int lane = tid & 31;
    const int G = blockIdx.x * 8 + wid;   // 0..1023, all active

    const int g  = lane >> 2;
    const int tg = lane & 3;
    const int base = G * 8;
    const float bo = boS;

    // ---- weight A-fragments, register-resident (36 tiles x 4 regs) ----
    uint32_t W0[3][2][2][4], Wi[3][2][2][4], Wh[3][2][2][4];
#pragma unroll
    for (int gate = 0; gate < 3; gate++)
#pragma unroll
        for (int mt = 0; mt < 2; mt++)
#pragma unroll
            for (int kt = 0; kt < 2; kt++)
#pragma unroll
                for (int aa = 0; aa < 4; aa++) {
                    int row = gate * 32 + mt * 16 + g + (aa & 1) * 8;
                    int col = kt * 16 + 2 * tg + (aa >> 1) * 8;
                    float2 v0 = *(const float2*)&Whh0[row * 32 + col];
                    float2 vi = *(const float2*)&Wih1[row * 32 + col];
                    float2 vh = *(const float2*)&Whh1[row * 32 + col];
                    W0[gate][mt][kt][aa] = pkh(v0.x, v0.y);
                    Wi[gate][mt][kt][aa] = pkh(vi.x, vi.y);
                    Wh[gate][mt][kt][aa] = pkh(vh.x, vh.y);
                }

    // ---- h masters (f32, D-layout) ----
    float h0D[2][4], h1D[2][4];
#pragma unroll
    for (int mt = 0; mt < 2; mt++)
#pragma unroll
        for (int rr = 0; rr < 2; rr++)
#pragma unroll
            for (int c = 0; c < 2; c++) {
                int u = 16 * mt + 8 * rr + g;
                int b = base + 2 * tg + c;
                h0D[mt][rr * 2 + c] = h_in[(size_t)b * 32 + u];
                h1D[mt][rr * 2 + c] = h_in[(size_t)(BATCH + b) * 32 + u];
            }

    // ---- B-fragments via transpose ----
    uint32_t hB0[4], hB1[4];
#pragma unroll
    for (int mt = 0; mt < 2; mt++) {
        hB0[mt * 2]     = movm(pkh(h0D[mt][0], h0D[mt][1]));
        hB0[mt * 2 + 1] = movm(pkh(h0D[mt][2], h0D[mt][3]));
        hB1[mt * 2]     = movm(pkh(h1D[mt][0], h1D[mt][1]));
        hB1[mt * 2 + 1] = movm(pkh(h1D[mt][2], h1D[mt][3]));
    }

    float2 xv = *(const float2*)&x[base + 2 * tg];

    for (int st = 0; st < SEQ; st++) {
        float2 xn = *(const float2*)&x[(size_t)min(st + 1, SEQ - 1) * BATCH + base + 2 * tg];

        // ===== HOISTED: L1 Wh x h1 contributions (independent of L0) =====
        float Er[2][4], Ez[2][4], Eh[2][4];
#pragma unroll
        for (int mt = 0; mt < 2; mt++) {
            mma16o(Er[mt], Wh[0][mt][0], hB1[0], hB1[1]);
            mma16 (Er[mt], Wh[0][mt][1], hB1[2], hB1[3]);
            mma16o(Ez[mt], Wh[1][mt][0], hB1[0], hB1[1]);
            mma16 (Ez[mt], Wh[1][mt][1], hB1[2], hB1[3]);
            mma16o(Eh[mt], Wh[2][mt][0], hB1[0], hB1[1]);
            mma16 (Eh[mt], Wh[2][mt][1], hB1[2], hB1[3]);
        }

        // ---------- layer 0: per-mt MMA + epilogue ----------
#pragma unroll
        for (int mt = 0; mt < 2; mt++) {
            float Dr[4], Dz[4], Dn[4];
            mma16o(Dr, W0[0][mt][0], hB0[0], hB0[1]);
            mma16 (Dr, W0[0][mt][1], hB0[2], hB0[3]);
            mma16o(Dz, W0[1][mt][0], hB0[0], hB0[1]);
            mma16 (Dz, W0[1][mt][1], hB0[2], hB0[3]);
            mma16o(Dn, W0[2][mt][0], hB0[0], hB0[1]);
            mma16 (Dn, W0[2][mt][1], hB0[2], hB0[3]);
#pragma unroll
            for (int rr = 0; rr < 2; rr++) {
                const int u = 16 * mt + 8 * rr + g;
                const float4 A  = KA[u];
                const float4 Bc = KB[u];
#pragma unroll
                for (int c = 0; c < 2; c++) {
                    const int di = rr * 2 + c;
                    const float xvc = c ? xv.y : xv.x;
                    float r = sig_t(fmaf(xvc, A.x, Dr[di] + Bc.x));
                    float z = sig_t(fmaf(xvc, A.y, Dz[di] + Bc.y));
                    float n = tanh_ap(fmaf(xvc, A.z, A.w) + r * (Dn[di] + Bc.z));
                    float hold = h0D[mt][di];
                    h0D[mt][di] = n + z * (hold - n);
                }
            }
        }
        // h0' -> B-frags (in-warp transpose)
#pragma unroll
        for (int mt = 0; mt < 2; mt++) {
            hB0[mt * 2]     = movm(pkh(h0D[mt][0], h0D[mt][1]));
            hB0[mt * 2 + 1] = movm(pkh(h0D[mt][2], h0D[mt][3]));
        }

        // ---------- layer 1: Wi x h0' appended, then epilogue ----------
        float y0 = 0.0f, y1 = 0.0f;
#pragma unroll
        for (int mt = 0; mt < 2; mt++) {
            float Ei[4];
            mma16 (Er[mt], Wi[0][mt][0], hB0[0], hB0[1]);
            mma16 (Er[mt], Wi[0][mt][1], hB0[2], hB0[3]);
            mma16 (Ez[mt], Wi[1][mt][0], hB0[0], hB0[1]);
            mma16 (Ez[mt], Wi[1][mt][1], hB0[2], hB0[3]);
            mma16o(Ei,     Wi[2][mt][0], hB0[0], hB0[1]);
            mma16 (Ei,     Wi[2][mt][1], hB0[2], hB0[3]);
#pragma unroll
            for (int rr = 0; rr < 2; rr++) {
                const int u = 16 * mt + 8 * rr + g;
                const float4 C = KC[u];
                const float wou = KB[u].w;
#pragma unroll
                for (int c = 0; c < 2; c++) {
                    const int di = rr * 2 + c;
                    float r = sig_t(Er[mt][di] + C.x);
                    float z = sig_t(Ez[mt][di] + C.y);
                    float n = tanh_ap(Ei[di] + C.z + r * (Eh[mt][di] + C.w));
                    float hold = h1D[mt][di];
                    float hn = n + z * (hold - n);
                    h1D[mt][di] = hn;
                    if (c) y1 = fmaf(hn, wou, y1); else y0 = fmaf(hn, wou, y0);
                }
            }
        }
        // h1' -> B-frags
#pragma unroll
        for (int mt = 0; mt < 2; mt++) {
            hB1[mt * 2]     = movm(pkh(h1D[mt][0], h1D[mt][1]));
            hB1[mt * 2 + 1] = movm(pkh(h1D[mt][2], h1D[mt][3]));
        }

        // y reduce over g (lane bits 2,3,4) and store
        y0 += __shfl_xor_sync(0xffffffffu, y0, 4);
        y0 += __shfl_xor_sync(0xffffffffu, y0, 8);
        y0 += __shfl_xor_sync(0xffffffffu, y0, 16);
        y1 += __shfl_xor_sync(0xffffffffu, y1, 4);
        y1 += __shfl_xor_sync(0xffffffffu, y1, 8);
        y1 += __shfl_xor_sync(0xffffffffu, y1, 16);
        if (lane < 4) {
            float2 yo = make_float2(y0 + bo, y1 + bo);
            *(float2*)&out[(size_t)st * BATCH + base + 2 * tg] = yo;
        }
        xv = xn;
    }

    // final h_state (2, B, 32)
    float* hout = out + (size_t)SEQ * BATCH;
#pragma unroll
    for (int mt = 0; mt < 2; mt++)
#pragma unroll
        for (int rr = 0; rr < 2; rr++)
#pragma unroll
            for (int c = 0; c < 2; c++) {
                int u = 16 * mt + 8 * rr + g;
                int b = base + 2 * tg + c;
                hout[(size_t)b * 32 + u] = h0D[mt][rr * 2 + c];
                hout[(size_t)(BATCH + b) * 32 + u] = h1D[mt][rr * 2 + c];
            }
}

extern "C" void kernel_launch(void* const* d_in, const int* in_sizes, int n_in,
                              void* d_out, int out_size) {
    (void)in_sizes; (void)n_in; (void)out_size;
    const float* x    = (const float*)d_in[0];
    const float* h    = (const float*)d_in[1];
    const float* Wih0 = (const float*)d_in[2];
    const float* Whh0 = (const float*)d_in[3];
    const float* bih0 = (const float*)d_in[4];
    const float* bhh0 = (const float*)d_in[5];
    const float* Wih1 = (const float*)d_in[6];
    const float* Whh1 = (const float*)d_in[7];
    const float* bih1 = (const float*)d_in[8];
    const float* bhh1 = (const float*)d_in[9];
    const float* Wout = (const float*)d_in[10];
    const float* bout = (const float*)d_in[11];

    // 128 blocks x 8 warps: 1024 warp-units, exactly 2 per SMSP, uniform
    gru2_wp5_kernel<<<128, 256>>>(x, h, Wih0, Whh0, bih0, bhh0,
                                  Wih1, Whh1, bih1, bhh1, Wout, bout,
                                  (float*)d_out);
}

// round 15
// speedup vs baseline: 1.1393x; 1.0429x over previous
#include <cuda_runtime.h>
#include <cuda_fp16.h>
#include <cstdint>

#define SEQ   256
#define BATCH 8192

// pack two f32 -> f16x2 (lo = first arg)
__device__ __forceinline__ uint32_t pkh(float lo, float hi) {
    uint32_t u; asm("cvt.rn.f16x2.f32 %0, %2, %1;" : "=r"(u) : "f"(lo), "f"(hi)); return u;
}
// 8x8 f16 in-warp transpose
__device__ __forceinline__ uint32_t movm(uint32_t s) {
    uint32_t d;
    asm("movmatrix.sync.aligned.m8n8.trans.b16 %0, %1;" : "=r"(d) : "r"(s));
    return d;
}
// D += A*B
__device__ __forceinline__ void mma16(float d[4], const uint32_t a[4],
                                      uint32_t b0, uint32_t b1) {
    asm("mma.sync.aligned.m16n8k16.row.col.f32.f16.f16.f32 "
        "{%0,%1,%2,%3},{%4,%5,%6,%7},{%8,%9},{%0,%1,%2,%3};"
        : "+f"(d[0]), "+f"(d[1]), "+f"(d[2]), "+f"(d[3])
        : "r"(a[0]), "r"(a[1]), "r"(a[2]), "r"(a[3]), "r"(b0), "r"(b1));
}
// D = A*B (fresh accumulator)
__device__ __forceinline__ void mma16o(float d[4], const uint32_t a[4],
                                       uint32_t b0, uint32_t b1) {
    asm("mma.sync.aligned.m16n8k16.row.col.f32.f16.f16.f32 "
        "{%0,%1,%2,%3},{%4,%5,%6,%7},{%8,%9},{%10,%10,%10,%10};"
        : "=f"(d[0]), "=f"(d[1]), "=f"(d[2]), "=f"(d[3])
        : "r"(a[0]), "r"(a[1]), "r"(a[2]), "r"(a[3]), "r"(b0), "r"(b1),
          "f"(0.0f));
}
// f32 gates: sigmoid(x) = 0.5*tanh(0.5x)+0.5
__device__ __forceinline__ float sig_t(float x) {
    float t; asm("tanh.approx.f32 %0, %1;" : "=f"(t) : "f"(0.5f * x));
    return fmaf(t, 0.5f, 0.5f);
}
__device__ __forceinline__ float tanh_ap(float x) {
    float t; asm("tanh.approx.f32 %0, %1;" : "=f"(t) : "f"(x)); return t;
}

// Grid: 148 blocks x 224 threads (7 warps). Warp-unit W = wid*148 + bid,
// active iff W < 1024; warp privately owns 8 batch columns [8W, 8W+8).
// D[hidden(m), batch(n)] = W[hidden,k] @ h[k,batch]; movmatrix recurrence.
// SOFTWARE PIPELINE: L0 MMAs for step t+1 issue right after movm(hB0'),
// so their latency hides under the entire L1 section of step t. The loop
// top is the L0 epilogue consuming the loop-carried Dr/Dz/Dn.
__global__ void __launch_bounds__(224, 1) gru2_wp6_kernel(
    const float* __restrict__ x,
    const float* __restrict__ h_in,
    const float* __restrict__ Wih0,
    const float* __restrict__ Whh0,
    const float* __restrict__ bih0,
    const float* __restrict__ bhh0,
    const float* __restrict__ Wih1,
    const float* __restrict__ Whh1,
    const float* __restrict__ bih1,
    const float* __restrict__ bhh1,
    const float* __restrict__ Wout,
    const float* __restrict__ bout,
    float* __restrict__ out)
{
    __shared__ float4 KA[32];   // (Wih0_r, Wih0_z, Wih0_n, bih0_n)
    __shared__ float4 KB[32];   // (br0c, bz0c, bhn0, Wout)
    __shared__ float4 KC[32];   // (br1c, bz1c, bin1, bhn1)
    __shared__ float  boS;

    const int tid = threadIdx.x;
    if (tid < 32) {
        int u = tid;
        KA[u] = make_float4(Wih0[u], Wih0[32 + u], Wih0[64 + u], bih0[64 + u]);
        KB[u] = make_float4(bih0[u] + bhh0[u], bih0[32 + u] + bhh0[32 + u],
                            bhh0[64 + u], Wout[u]);
        KC[u] = make_float4(bih1[u] + bhh1[u], bih1[32 + u] + bhh1[32 + u],
                            bih1[64 + u], bhh1[64 + u]);
    }
    if (tid == 0) boS = bout[0];
    __syncthreads();

    const int wid  = tid >> 5;
    const int lane = tid & 31;
    const int W = wid * 148 + blockIdx.x;
    if (W >= 1024) return;

    const int g  = lane >> 2;
    const int tg = lane & 3;
    const int base = W * 8;
    const float bo = boS;

    // ---- weight A-fragments, register-resident (36 tiles x 4 regs) ----
    uint32_t W0[3][2][2][4], Wi[3][2][2][4], Wh[3][2][2][4];
#pragma unroll
    for (int gate = 0; gate < 3; gate++)
#pragma unroll
        for (int mt = 0; mt < 2; mt++)
#pragma unroll
            for (int kt = 0; kt < 2; kt++)
#pragma unroll
                for (int aa = 0; aa < 4; aa++) {
                    int row = gate * 32 + mt * 16 + g + (aa & 1) * 8;
                    int col = kt * 16 + 2 * tg + (aa >> 1) * 8;
                    float2 v0 = *(const float2*)&Whh0[row * 32 + col];
                    float2 vi = *(const float2*)&Wih1[row * 32 + col];
                    float2 vh = *(const float2*)&Whh1[row * 32 + col];
                    W0[gate][mt][kt][aa] = pkh(v0.x, v0.y);
                    Wi[gate][mt][kt][aa] = pkh(vi.x, vi.y);
                    Wh[gate][mt][kt][aa] = pkh(vh.x, vh.y);
                }

    // ---- h masters (f32, D-layout) ----
    float h0D[2][4], h1D[2][4];
#pragma unroll
    for (int mt = 0; mt < 2; mt++)
#pragma unroll
        for (int rr = 0; rr < 2; rr++)
#pragma unroll
            for (int c = 0; c < 2; c++) {
                int u = 16 * mt + 8 * rr + g;
                int b = base + 2 * tg + c;
                h0D[mt][rr * 2 + c] = h_in[(size_t)b * 32 + u];
                h1D[mt][rr * 2 + c] = h_in[(size_t)(BATCH + b) * 32 + u];
            }

    // ---- B-fragments via transpose ----
    uint32_t hB0[4], hB1[4];
#pragma unroll
    for (int mt = 0; mt < 2; mt++) {
        hB0[mt * 2]     = movm(pkh(h0D[mt][0], h0D[mt][1]));
        hB0[mt * 2 + 1] = movm(pkh(h0D[mt][2], h0D[mt][3]));
        hB1[mt * 2]     = movm(pkh(h1D[mt][0], h1D[mt][1]));
        hB1[mt * 2 + 1] = movm(pkh(h1D[mt][2], h1D[mt][3]));
    }

    float2 xv = *(const float2*)&x[base + 2 * tg];

    // ---- preamble: L0 MMAs for step 0 (loop-carried accumulators) ----
    float Dr[2][4], Dz[2][4], Dn[2][4];
#pragma unroll
    for (int mt = 0; mt < 2; mt++) {
        mma16o(Dr[mt], W0[0][mt][0], hB0[0], hB0[1]);
        mma16 (Dr[mt], W0[0][mt][1], hB0[2], hB0[3]);
        mma16o(Dz[mt], W0[1][mt][0], hB0[0], hB0[1]);
        mma16 (Dz[mt], W0[1][mt][1], hB0[2], hB0[3]);
        mma16o(Dn[mt], W0[2][mt][0], hB0[0], hB0[1]);
        mma16 (Dn[mt], W0[2][mt][1], hB0[2], hB0[3]);
    }

    for (int st = 0; st < SEQ; st++) {
        float2 xn = *(const float2*)&x[(size_t)min(st + 1, SEQ - 1) * BATCH + base + 2 * tg];

        // ---------- layer 0 epilogue for step st (consumes pipelined D) ----------
#pragma unroll
        for (int mt = 0; mt < 2; mt++)
#pragma unroll
            for (int rr = 0; rr < 2; rr++) {
                const int u = 16 * mt + 8 * rr + g;
                const float4 A  = KA[u];
                const float4 Bc = KB[u];
#pragma unroll
                for (int c = 0; c < 2; c++) {
                    const int di = rr * 2 + c;
                    const float xvc = c ? xv.y : xv.x;
                    float r = sig_t(fmaf(xvc, A.x, Dr[mt][di] + Bc.x));
                    float z = sig_t(fmaf(xvc, A.y, Dz[mt][di] + Bc.y));
                    float n = tanh_ap(fmaf(xvc, A.z, A.w) + r * (Dn[mt][di] + Bc.z));
                    float hold = h0D[mt][di];
                    h0D[mt][di] = n + z * (hold - n);
                }
            }
        // h0' -> B-frags (in-warp transpose)
#pragma unroll
        for (int mt = 0; mt < 2; mt++) {
            hB0[mt * 2]     = movm(pkh(h0D[mt][0], h0D[mt][1]));
            hB0[mt * 2 + 1] = movm(pkh(h0D[mt][2], h0D[mt][3]));
        }

        // ===== PIPELINED: issue L0 MMAs for step st+1 NOW; their latency =====
        // ===== hides under the entire L1 section below.                   =====
#pragma unroll
        for (int mt = 0; mt < 2; mt++) {
            mma16o(Dr[mt], W0[0][mt][0], hB0[0], hB0[1]);
            mma16 (Dr[mt], W0[0][mt][1], hB0[2], hB0[3]);
            mma16o(Dz[mt], W0[1][mt][0], hB0[0], hB0[1]);
            mma16 (Dz[mt], W0[1][mt][1], hB0[2], hB0[3]);
            mma16o(Dn[mt], W0[2][mt][0], hB0[0], hB0[1]);
            mma16 (Dn[mt], W0[2][mt][1], hB0[2], hB0[3]);
        }

        // ---------- layer 1: per-mt transient accumulators ----------
        float y0 = 0.0f, y1 = 0.0f;
#pragma unroll
        for (int mt = 0; mt < 2; mt++) {
            float Er[4], Ez[4], Ei[4], Eh[4];
            mma16o(Er, Wh[0][mt][0], hB1[0], hB1[1]);
            mma16 (Er, Wh[0][mt][1], hB1[2], hB1[3]);
            mma16 (Er, Wi[0][mt][0], hB0[0], hB0[1]);
            mma16 (Er, Wi[0][mt][1], hB0[2], hB0[3]);
            mma16o(Ez, Wh[1][mt][0], hB1[0], hB1[1]);
            mma16 (Ez, Wh[1][mt][1], hB1[2], hB1[3]);
            mma16 (Ez, Wi[1][mt][0], hB0[0], hB0[1]);
            mma16 (Ez, Wi[1][mt][1], hB0[2], hB0[3]);
            mma16o(Ei, Wi[2][mt][0], hB0[0], hB0[1]);
            mma16 (Ei, Wi[2][mt][1], hB0[2], hB0[3]);
            mma16o(Eh, Wh[2][mt][0], hB1[0], hB1[1]);
            mma16 (Eh, Wh[2][mt][1], hB1[2], hB1[3]);
#pragma unroll
            for (int rr = 0; rr < 2; rr++) {
                const int u = 16 * mt + 8 * rr + g;
                const float4 C = KC[u];
                const float wou = KB[u].w;
#pragma unroll
                for (int c = 0; c < 2; c++) {
                    const int di = rr * 2 + c;
                    float r = sig_t(Er[di] + C.x);
                    float z = sig_t(Ez[di] + C.y);
                    float n = tanh_ap(Ei[di] + C.z + r * (Eh[di] + C.w));
                    float hold = h1D[mt][di];
                    float hn = n + z * (hold - n);
                    h1D[mt][di] = hn;
                    if (c) y1 = fmaf(hn, wou, y1); else y0 = fmaf(hn, wou, y0);
                }
            }
        }
        // h1' -> B-frags
#pragma unroll
        for (int mt = 0; mt < 2; mt++) {
            hB1[mt * 2]     = movm(pkh(h1D[mt][0], h1D[mt][1]));
            hB1[mt * 2 + 1] = movm(pkh(h1D[mt][2], h1D[mt][3]));
        }

        // y reduce over g (lane bits 2,3,4) and store
        y0 += __shfl_xor_sync(0xffffffffu, y0, 4);
        y0 += __shfl_xor_sync(0xffffffffu, y0, 8);
        y0 += __shfl_xor_sync(0xffffffffu, y0, 16);
        y1 += __shfl_xor_sync(0xffffffffu, y1, 4);
        y1 += __shfl_xor_sync(0xffffffffu, y1, 8);
        y1 += __shfl_xor_sync(0xffffffffu, y1, 16);
        if (lane < 4) {
            float2 yo = make_float2(y0 + bo, y1 + bo);
            *(float2*)&out[(size_t)st * BATCH + base + 2 * tg] = yo;
        }
        xv = xn;
    }

    // final h_state (2, B, 32)
    float* hout = out + (size_t)SEQ * BATCH;
#pragma unroll
    for (int mt = 0; mt < 2; mt++)
#pragma unroll
        for (int rr = 0; rr < 2; rr++)
#pragma unroll
            for (int c = 0; c < 2; c++) {
                int u = 16 * mt + 8 * rr + g;
                int b = base + 2 * tg + c;
                hout[(size_t)b * 32 + u] = h0D[mt][rr * 2 + c];
                hout[(size_t)(BATCH + b) * 32 + u] = h1D[mt][rr * 2 + c];
            }
}

extern "C" void kernel_launch(void* const* d_in, const int* in_sizes, int n_in,
                              void* d_out, int out_size) {
    (void)in_sizes; (void)n_in; (void)out_size;
    const float* x    = (const float*)d_in[0];
    const float* h    = (const float*)d_in[1];
    const float* Wih0 = (const float*)d_in[2];
    const float* Whh0 = (const float*)d_in[3];
    const float* bih0 = (const float*)d_in[4];
    const float* bhh0 = (const float*)d_in[5];
    const float* Wih1 = (const float*)d_in[6];
    const float* Whh1 = (const float*)d_in[7];
    const float* bih1 = (const float*)d_in[8];
    const float* bhh1 = (const float*)d_in[9];
    const float* Wout = (const float*)d_in[10];
    const float* bout = (const float*)d_in[11];

    // 148 blocks x 7 warps: 1024 warp-units x 8 batch = 8192; barrier-free loop
    gru2_wp6_kernel<<<148, 224>>>(x, h, Wih0, Whh0, bih0, bhh0,
                                  Wih1, Whh1, bih1, bhh1, Wout, bout,
                                  (float*)d_out);
}